// round 13
// baseline (speedup 1.0000x reference)
#include <cuda_runtime.h>

// Sizes: x (256,4096) f32, weights (64,64,64) f32, out (256,4096) f32.
// out[b, f*64+n] = sum_c sum_m w[f,c,m] * x[b, c*64 + (n-m) mod 64]
// computed in the 64-point DFT domain with rfft symmetry (33 freqs).

#define NF 33
#define BSZ 256
#define CC 64
#define FF 64

// [k][row] planes. Wf rows = f*64+c (4096), Xf rows = b*64+c (16384),
// S rows = b*64+f (16384).
__device__ float2 g_Wf[NF * FF * CC];
__device__ float2 g_Xf[NF * BSZ * CC];
__device__ float2 g_S [NF * BSZ * FF];

// ---------------------------------------------------------------------------
// Kernel 1: forward rDFT of every length-64 row (4096 w-rows + 16384 x-rows).
// Radix-2 m-split + j-fold (X = P + (-i)^k Q); lane k keeps its 16 basis
// values in registers; hot loop = 2 broadcast LDS.128 + 16 reg-FMA per j.
// X[32] = parity sum from staging phase. Row LDG hoisted to kernel entry so
// DRAM latency overlaps the twiddle/basis smem fills.
// CTA = 32 rows x 256 thr (warp = 4 rows, lane = k), grid 640.
// ---------------------------------------------------------------------------
__global__ void __launch_bounds__(256, 4) k_dft(const float* __restrict__ x,
                                                const float* __restrict__ w) {
    __shared__ float  esm[32][36];    // [j][r]
    __shared__ float  osm[32][36];
    __shared__ float  psm[8][36];     // [hq][r] parity partials
    __shared__ float2 Bsm[16][33];    // [j][k], j < 16
    __shared__ float2 outsm[33][34];  // [k][r]
    __shared__ float2 tw[64];

    const int t = threadIdx.x;
    const int warp = t >> 5, lane = t & 31;

    const int row0 = blockIdx.x * 32;
    const bool isW = row0 < FF * CC;          // first 128 CTAs exactly
    const float* src = isW ? (w + row0 * 64) : (x + (row0 - FF * CC) * 64);
    float2* base = isW ? g_Wf : g_Xf;
    const int plane = isW ? (FF * CC) : (BSZ * CC);
    const int roff = isW ? row0 : (row0 - FF * CC);

    // ---- issue row LDG immediately (thread = row r, quarter hq) ----
    const int r  = t >> 3;       // 0..31
    const int hq = t & 7;
    const float4* s4 = (const float4*)src;
    const float4 a  = s4[r * 16 + hq];
    const float4 bq = s4[r * 16 + hq + 8];

    // ---- twiddle + basis fills overlap the LDG latency ----
    if (t < 64) {
        float s, c;
        sincospif(-(float)t * (1.0f / 32.0f), &s, &c);
        tw[t] = make_float2(c, s);
    }
    __syncthreads();
#pragma unroll
    for (int i = t; i < 512; i += 256) {
        const int j = i >> 5, k = i & 31;
        Bsm[j][k] = tw[(j * k) & 63];
    }

    // ---- radix-2 pre-sums (consume LDG) ----
    {
        const float e0 = a.x + bq.x, e1 = a.y + bq.y;
        const float e2 = a.z + bq.z, e3 = a.w + bq.w;
        esm[4 * hq + 0][r] = e0;  osm[4 * hq + 0][r] = a.x - bq.x;
        esm[4 * hq + 1][r] = e1;  osm[4 * hq + 1][r] = a.y - bq.y;
        esm[4 * hq + 2][r] = e2;  osm[4 * hq + 2][r] = a.z - bq.z;
        esm[4 * hq + 3][r] = e3;  osm[4 * hq + 3][r] = a.w - bq.w;
        psm[hq][r] = e0 - e1 + e2 - e3;       // j = 4hq starts even
    }
    __syncthreads();

    // ---- k = 32 plane into outsm ----
    if (t < 32) {
        float p = 0.0f;
#pragma unroll
        for (int q = 0; q < 8; q++) p += psm[q][t];
        outsm[32][t] = make_float2(p, 0.0f);
    }

    // ---- basis for this lane into registers ----
    float2 B[16];
#pragma unroll
    for (int j = 0; j < 16; j++) B[j] = Bsm[j][lane];

    // ---- compute: warp = 4 rows, lane = frequency k ----
    const int r0 = warp * 4;
    const float* ub = (lane & 1) ? &osm[0][0] : &esm[0][0];

    float Pr[4] = {}, Pi[4] = {}, Qr[4] = {}, Qi[4] = {};
#pragma unroll
    for (int j = 0; j < 16; j++) {
        const float4 vP = *(const float4*)(ub + j * 36 + r0);
        const float4 vQ = *(const float4*)(ub + (j + 16) * 36 + r0);
        const float br = B[j].x, bi = B[j].y;
        Pr[0] = fmaf(vP.x, br, Pr[0]);  Pi[0] = fmaf(vP.x, bi, Pi[0]);
        Pr[1] = fmaf(vP.y, br, Pr[1]);  Pi[1] = fmaf(vP.y, bi, Pi[1]);
        Pr[2] = fmaf(vP.z, br, Pr[2]);  Pi[2] = fmaf(vP.z, bi, Pi[2]);
        Pr[3] = fmaf(vP.w, br, Pr[3]);  Pi[3] = fmaf(vP.w, bi, Pi[3]);
        Qr[0] = fmaf(vQ.x, br, Qr[0]);  Qi[0] = fmaf(vQ.x, bi, Qi[0]);
        Qr[1] = fmaf(vQ.y, br, Qr[1]);  Qi[1] = fmaf(vQ.y, bi, Qi[1]);
        Qr[2] = fmaf(vQ.z, br, Qr[2]);  Qi[2] = fmaf(vQ.z, bi, Qi[2]);
        Qr[3] = fmaf(vQ.w, br, Qr[3]);  Qi[3] = fmaf(vQ.w, bi, Qi[3]);
    }

    // ---- fold combine: X = P + (-i)^k Q ----
    {
        const bool sw = (lane & 1);
        const float s1 = (lane & 2) ? -1.0f : 1.0f;
        const float s2 = ((lane + 1) & 2) ? -1.0f : 1.0f;
        float ar[4], ai[4];
#pragma unroll
        for (int m = 0; m < 4; m++) {
            const float t1 = sw ? Qi[m] : Qr[m];
            const float t2 = sw ? Qr[m] : Qi[m];
            ar[m] = fmaf(s1, t1, Pr[m]);
            ai[m] = fmaf(s2, t2, Pi[m]);
        }
        float4* o4 = (float4*)&outsm[lane][r0];
        o4[0] = make_float4(ar[0], ai[0], ar[1], ai[1]);
        o4[1] = make_float4(ar[2], ai[2], ar[3], ai[3]);
    }
    __syncthreads();

    // ---- coalesced stores: 256B runs within each k plane ----
#pragma unroll
    for (int i = t; i < 33 * 32; i += 256) {
        const int k = i >> 5, rl = i & 31;
        base[k * plane + roff + rl] = outsm[k][rl];
    }
}

// ---------------------------------------------------------------------------
// Kernel 2: per-frequency complex GEMM, Karatsuba 3-mult.
// Grid (8 btiles x 2 ftiles, 33) = 528 CTAs, 256 thr, smem ~51KB ->
// 4 CTAs/SM resident. Tile 32b x 32f over 64 c; thread = 2b x 2f.
// W/Wsum stored transposed [c][f] (pitch 33/35): compute loads contiguous
// (1 phase), X loads are 2-address broadcasts.
//   Re = a1 - a2,  Im = a3 - a1 - a2
//   a1 = sum xr*wr, a2 = sum xi*wi, a3 = sum (xr+xi)*(wr+wi)
// ---------------------------------------------------------------------------
__global__ void __launch_bounds__(256) k_gemm() {
    extern __shared__ float smf[];
    float2* Xs    = (float2*)smf;                        // [32][66]
    float*  Xsum  = smf + 2 * 32 * 66;                   // [32][68]
    float2* Wt    = (float2*)(smf + 2 * 32 * 66 + 32 * 68);    // [64c][33f]
    float*  Wsumt = smf + 2 * 32 * 66 + 32 * 68 + 2 * 64 * 33; // [64c][35f]

    const int k  = blockIdx.y;
    const int b0 = (blockIdx.x & 7) * 32;
    const int f0 = (blockIdx.x >> 3) * 32;
    const float2* gX = g_Xf + k * (BSZ * CC) + b0 * CC;
    const float2* gW = g_Wf + k * (FF * CC) + f0 * CC;

#pragma unroll
    for (int i = threadIdx.x; i < 2048; i += 256) {
        const int r = i >> 6, c = i & 63;
        const float2 xv = gX[i];
        Xs[r * 66 + c] = xv;
        Xsum[r * 68 + c] = xv.x + xv.y;
        const float2 wv = gW[i];
        Wt[c * 33 + r] = wv;
        Wsumt[c * 35 + r] = wv.x + wv.y;
    }
    __syncthreads();

    const int tf = threadIdx.x & 15;   // f = f0 + tf + 16*i (i<2)
    const int tb = threadIdx.x >> 4;   // b = b0 + tb + 16*j (j<2)

    float a1[2][2] = {}, a2[2][2] = {}, a3[2][2] = {};
#pragma unroll 4
    for (int c = 0; c < 64; c += 2) {
        float4 xv[2];
        float2 xs[2];
#pragma unroll
        for (int j = 0; j < 2; j++) {
            const int b = tb + 16 * j;
            xv[j] = *(const float4*)&Xs[b * 66 + c];      // (re,im) x 2 c's
            xs[j] = *(const float2*)&Xsum[b * 68 + c];
        }
        float2 w0[2], w1[2];
        float  ws0[2], ws1[2];
#pragma unroll
        for (int i = 0; i < 2; i++) {
            const int f = tf + 16 * i;
            w0[i]  = Wt[c * 33 + f];
            w1[i]  = Wt[(c + 1) * 33 + f];
            ws0[i] = Wsumt[c * 35 + f];
            ws1[i] = Wsumt[(c + 1) * 35 + f];
        }
#pragma unroll
        for (int j = 0; j < 2; j++)
#pragma unroll
            for (int i = 0; i < 2; i++) {
                a1[j][i] = fmaf(xv[j].x, w0[i].x, a1[j][i]);
                a2[j][i] = fmaf(xv[j].y, w0[i].y, a2[j][i]);
                a3[j][i] = fmaf(xs[j].x, ws0[i],  a3[j][i]);
                a1[j][i] = fmaf(xv[j].z, w1[i].x, a1[j][i]);
                a2[j][i] = fmaf(xv[j].w, w1[i].y, a2[j][i]);
                a3[j][i] = fmaf(xs[j].y, ws1[i],  a3[j][i]);
            }
    }

    float2* gS = g_S + k * (BSZ * FF) + b0 * FF + f0;
#pragma unroll
    for (int j = 0; j < 2; j++)
#pragma unroll
        for (int i = 0; i < 2; i++) {
            const float re = a1[j][i] - a2[j][i];
            const float im = a3[j][i] - a1[j][i] - a2[j][i];
            gS[(tb + 16 * j) * FF + tf + 16 * i] = make_float2(re, im);
        }
}

// ---------------------------------------------------------------------------
// Kernel 3: real inverse transform with n / n+32 symmetry:
//   out[r][n]    = E[r][n] + O[r][n]
//   out[r][n+32] = E[r][n] - O[r][n]      (n < 32)
//   E over even k, O over odd k, Bm[k][n] = (s_k cos, -s_k sin),
//   s_k = 1/64 for k in {0,32} else 2/64.
// CTA = 32 rows x 256 thr -> 512 CTAs (~3.5/SM). Thread = (row, 4-wide n).
// ---------------------------------------------------------------------------
__global__ void __launch_bounds__(256) k_inv(float* __restrict__ out) {
    __shared__ float2 Ssh[32][NF];   // [row][k]
    __shared__ float2 Bm[NF][32];    // n < 32 only
    __shared__ float2 tw[64];

    const int t = threadIdx.x;
    if (t < 64) {
        float s, c;
        sincospif((float)t * (1.0f / 32.0f), &s, &c);
        tw[t] = make_float2(c, s);
    }
    __syncthreads();
#pragma unroll
    for (int i = t; i < NF * 32; i += 256) {
        const int k = i >> 5, n = i & 31;
        const float sc = (k == 0 || k == 32) ? (1.0f / 64.0f) : (2.0f / 64.0f);
        const float2 wv = tw[(k * n) & 63];
        Bm[k][n] = make_float2(sc * wv.x, -sc * wv.y);
    }

    const int r0 = blockIdx.x * 32;
#pragma unroll
    for (int i = t; i < 32 * NF; i += 256) {
        const int rl = i & 31, k = i >> 5;
        Ssh[rl][k] = g_S[k * (BSZ * FF) + r0 + rl];
    }
    __syncthreads();

    const int ng  = t & 7;    // n = ng*4 .. ng*4+3 (lower half)
    const int row = t >> 3;   // 0..31

    float e[4] = {}, o[4] = {};
#pragma unroll
    for (int kk = 0; kk < 17; kk++) {          // even k = 0,2,...,32
        const int k = 2 * kk;
        const float2 sv = Ssh[row][k];
        const float4 b01 = *(const float4*)&Bm[k][ng * 4];
        const float4 b23 = *(const float4*)&Bm[k][ng * 4 + 2];
        e[0] = fmaf(sv.x, b01.x, e[0]);  e[0] = fmaf(sv.y, b01.y, e[0]);
        e[1] = fmaf(sv.x, b01.z, e[1]);  e[1] = fmaf(sv.y, b01.w, e[1]);
        e[2] = fmaf(sv.x, b23.x, e[2]);  e[2] = fmaf(sv.y, b23.y, e[2]);
        e[3] = fmaf(sv.x, b23.z, e[3]);  e[3] = fmaf(sv.y, b23.w, e[3]);
    }
#pragma unroll
    for (int kk = 0; kk < 16; kk++) {          // odd k = 1,3,...,31
        const int k = 2 * kk + 1;
        const float2 sv = Ssh[row][k];
        const float4 b01 = *(const float4*)&Bm[k][ng * 4];
        const float4 b23 = *(const float4*)&Bm[k][ng * 4 + 2];
        o[0] = fmaf(sv.x, b01.x, o[0]);  o[0] = fmaf(sv.y, b01.y, o[0]);
        o[1] = fmaf(sv.x, b01.z, o[1]);  o[1] = fmaf(sv.y, b01.w, o[1]);
        o[2] = fmaf(sv.x, b23.x, o[2]);  o[2] = fmaf(sv.y, b23.y, o[2]);
        o[3] = fmaf(sv.x, b23.z, o[3]);  o[3] = fmaf(sv.y, b23.w, o[3]);
    }

    float* obase = out + (r0 + row) * 64 + ng * 4;
    *(float4*)obase = make_float4(e[0] + o[0], e[1] + o[1],
                                  e[2] + o[2], e[3] + o[3]);
    *(float4*)(obase + 32) = make_float4(e[0] - o[0], e[1] - o[1],
                                         e[2] - o[2], e[3] - o[3]);
}

// ---------------------------------------------------------------------------
extern "C" void kernel_launch(void* const* d_in, const int* in_sizes, int n_in,
                              void* d_out, int out_size) {
    const float* x = (const float*)d_in[0];
    const float* w = (const float*)d_in[1];
    // Defensive: identify by element count (x = 1048576, w = 262144).
    if (n_in >= 2 && in_sizes[0] == 64 * 64 * 64) {
        x = (const float*)d_in[1];
        w = (const float*)d_in[0];
    }

    // Xs 16896 + Xsum 8704 + Wt 16896 + Wsumt 8960 = 51456 bytes
    static const size_t gemm_smem =
        (2 * 32 * 66 + 32 * 68 + 2 * 64 * 33 + 64 * 35) * sizeof(float);
    cudaFuncSetAttribute(k_gemm, cudaFuncAttributeMaxDynamicSharedMemorySize,
                         (int)gemm_smem);

    // 20480 rows total (4096 weight rows + 16384 x rows), 32 rows per CTA.
    k_dft<<<640, 256>>>(x, w);
    k_gemm<<<dim3(16, 33), 256, gemm_smem>>>();
    k_inv<<<512, 256>>>((float*)d_out);
}

// round 14
// speedup vs baseline: 1.1509x; 1.1509x over previous
#include <cuda_runtime.h>

// Sizes: x (256,4096) f32, weights (64,64,64) f32, out (256,4096) f32.
// out[b, f*64+n] = sum_c sum_m w[f,c,m] * x[b, c*64 + (n-m) mod 64]
// computed in the 64-point DFT domain with rfft symmetry (33 freqs).

#define NF 33
#define BSZ 256
#define CC 64
#define FF 64

// [k][row] planes. Wf rows = f*64+c (4096), Xf rows = b*64+c (16384),
// S rows = b*64+f (16384).
__device__ float2 g_Wf[NF * FF * CC];
__device__ float2 g_Xf[NF * BSZ * CC];
__device__ float2 g_S [NF * BSZ * FF];

// ---------------------------------------------------------------------------
// Kernel 1: forward rDFT of every length-64 row (4096 w-rows + 16384 x-rows).
// Radix-2 m-split + j-fold (X = P + (-i)^k Q); lane k keeps its 16 basis
// values in registers. CTA = 32 rows x 128 thr (warp = 8 rows, lane = k),
// grid 640, <=5 CTAs/SM -> the ENTIRE kernel is one wave (740 slots >= 640).
// Hot loop per j: 4 broadcast LDS.128 + 32 reg-FMA. Row LDG hoisted to
// kernel entry to overlap the twiddle/basis fills.
// ---------------------------------------------------------------------------
__global__ void __launch_bounds__(128, 5) k_dft(const float* __restrict__ x,
                                                const float* __restrict__ w) {
    __shared__ float  esm[32][36];    // [j][r]
    __shared__ float  osm[32][36];
    __shared__ float  psm[4][36];     // [q][r] parity partials
    __shared__ float2 Bsm[16][33];    // [j][k], j < 16
    __shared__ float2 outsm[33][34];  // [k][r]
    __shared__ float2 tw[64];

    const int t = threadIdx.x;
    const int warp = t >> 5, lane = t & 31;

    const int row0 = blockIdx.x * 32;
    const bool isW = row0 < FF * CC;          // first 128 CTAs exactly
    const float* src = isW ? (w + row0 * 64) : (x + (row0 - FF * CC) * 64);
    float2* base = isW ? g_Wf : g_Xf;
    const int plane = isW ? (FF * CC) : (BSZ * CC);
    const int roff = isW ? row0 : (row0 - FF * CC);

    // ---- issue row LDGs immediately (thread = row r, quarter-pair q) ----
    const int r = t >> 2, q = t & 3;
    const float4* s4 = (const float4*)src;
    const float4 aA = s4[r * 16 + q];          // floats [4q   .. 4q+4)
    const float4 bA = s4[r * 16 + q + 8];      // partner (+32)
    const float4 aB = s4[r * 16 + q + 4];      // floats [4q+16.. 4q+20)
    const float4 bB = s4[r * 16 + q + 12];     // partner (+32)

    // ---- twiddle + basis fills overlap the LDG latency ----
    if (t < 64) {
        float s, c;
        sincospif(-(float)t * (1.0f / 32.0f), &s, &c);
        tw[t] = make_float2(c, s);
    }
    __syncthreads();
#pragma unroll
    for (int i = t; i < 512; i += 128) {
        const int j = i >> 5, k = i & 31;
        Bsm[j][k] = tw[(j * k) & 63];
    }

    // ---- radix-2 pre-sums (consume LDGs) ----
    {
        const float eA0 = aA.x + bA.x, eA1 = aA.y + bA.y;
        const float eA2 = aA.z + bA.z, eA3 = aA.w + bA.w;
        esm[4 * q + 0][r] = eA0;  osm[4 * q + 0][r] = aA.x - bA.x;
        esm[4 * q + 1][r] = eA1;  osm[4 * q + 1][r] = aA.y - bA.y;
        esm[4 * q + 2][r] = eA2;  osm[4 * q + 2][r] = aA.z - bA.z;
        esm[4 * q + 3][r] = eA3;  osm[4 * q + 3][r] = aA.w - bA.w;
        const float eB0 = aB.x + bB.x, eB1 = aB.y + bB.y;
        const float eB2 = aB.z + bB.z, eB3 = aB.w + bB.w;
        esm[4 * q + 16][r] = eB0;  osm[4 * q + 16][r] = aB.x - bB.x;
        esm[4 * q + 17][r] = eB1;  osm[4 * q + 17][r] = aB.y - bB.y;
        esm[4 * q + 18][r] = eB2;  osm[4 * q + 18][r] = aB.z - bB.z;
        esm[4 * q + 19][r] = eB3;  osm[4 * q + 19][r] = aB.w - bB.w;
        // parity: j = 4q and 4q+16 both start even -> +,-,+,-
        psm[q][r] = (eA0 - eA1 + eA2 - eA3) + (eB0 - eB1 + eB2 - eB3);
    }
    __syncthreads();

    // ---- k = 32 plane into outsm ----
    if (t < 32) {
        const float p = psm[0][t] + psm[1][t] + psm[2][t] + psm[3][t];
        outsm[32][t] = make_float2(p, 0.0f);
    }

    // ---- basis for this lane into registers ----
    float2 B[16];
#pragma unroll
    for (int j = 0; j < 16; j++) B[j] = Bsm[j][lane];

    // ---- compute: warp = 8 rows, lane = frequency k ----
    const int r0 = warp * 8;
    const float* ub = (lane & 1) ? &osm[0][0] : &esm[0][0];

    float Pr[8] = {}, Pi[8] = {}, Qr[8] = {}, Qi[8] = {};
#pragma unroll
    for (int j = 0; j < 16; j++) {
        const float4 vPa = *(const float4*)(ub + j * 36 + r0);
        const float4 vPb = *(const float4*)(ub + j * 36 + r0 + 4);
        const float4 vQa = *(const float4*)(ub + (j + 16) * 36 + r0);
        const float4 vQb = *(const float4*)(ub + (j + 16) * 36 + r0 + 4);
        const float br = B[j].x, bi = B[j].y;
        Pr[0] = fmaf(vPa.x, br, Pr[0]);  Pi[0] = fmaf(vPa.x, bi, Pi[0]);
        Pr[1] = fmaf(vPa.y, br, Pr[1]);  Pi[1] = fmaf(vPa.y, bi, Pi[1]);
        Pr[2] = fmaf(vPa.z, br, Pr[2]);  Pi[2] = fmaf(vPa.z, bi, Pi[2]);
        Pr[3] = fmaf(vPa.w, br, Pr[3]);  Pi[3] = fmaf(vPa.w, bi, Pi[3]);
        Pr[4] = fmaf(vPb.x, br, Pr[4]);  Pi[4] = fmaf(vPb.x, bi, Pi[4]);
        Pr[5] = fmaf(vPb.y, br, Pr[5]);  Pi[5] = fmaf(vPb.y, bi, Pi[5]);
        Pr[6] = fmaf(vPb.z, br, Pr[6]);  Pi[6] = fmaf(vPb.z, bi, Pi[6]);
        Pr[7] = fmaf(vPb.w, br, Pr[7]);  Pi[7] = fmaf(vPb.w, bi, Pi[7]);
        Qr[0] = fmaf(vQa.x, br, Qr[0]);  Qi[0] = fmaf(vQa.x, bi, Qi[0]);
        Qr[1] = fmaf(vQa.y, br, Qr[1]);  Qi[1] = fmaf(vQa.y, bi, Qi[1]);
        Qr[2] = fmaf(vQa.z, br, Qr[2]);  Qi[2] = fmaf(vQa.z, bi, Qi[2]);
        Qr[3] = fmaf(vQa.w, br, Qr[3]);  Qi[3] = fmaf(vQa.w, bi, Qi[3]);
        Qr[4] = fmaf(vQb.x, br, Qr[4]);  Qi[4] = fmaf(vQb.x, bi, Qi[4]);
        Qr[5] = fmaf(vQb.y, br, Qr[5]);  Qi[5] = fmaf(vQb.y, bi, Qi[5]);
        Qr[6] = fmaf(vQb.z, br, Qr[6]);  Qi[6] = fmaf(vQb.z, bi, Qi[6]);
        Qr[7] = fmaf(vQb.w, br, Qr[7]);  Qi[7] = fmaf(vQb.w, bi, Qi[7]);
    }

    // ---- fold combine: X = P + (-i)^k Q ----
    {
        const bool sw = (lane & 1);
        const float s1 = (lane & 2) ? -1.0f : 1.0f;
        const float s2 = ((lane + 1) & 2) ? -1.0f : 1.0f;
        float4* o4 = (float4*)&outsm[lane][r0];
#pragma unroll
        for (int u = 0; u < 4; u++) {
            const int m0 = 2 * u, m1 = 2 * u + 1;
            const float t10 = sw ? Qi[m0] : Qr[m0];
            const float t20 = sw ? Qr[m0] : Qi[m0];
            const float t11 = sw ? Qi[m1] : Qr[m1];
            const float t21 = sw ? Qr[m1] : Qi[m1];
            o4[u] = make_float4(fmaf(s1, t10, Pr[m0]), fmaf(s2, t20, Pi[m0]),
                                fmaf(s1, t11, Pr[m1]), fmaf(s2, t21, Pi[m1]));
        }
    }
    __syncthreads();

    // ---- coalesced stores: 256B runs within each k plane ----
#pragma unroll
    for (int i = t; i < 33 * 32; i += 128) {
        const int k = i >> 5, rl = i & 31;
        base[k * plane + roff + rl] = outsm[k][rl];
    }
}

// ---------------------------------------------------------------------------
// Kernel 2: per-frequency complex GEMM, Karatsuba 3-mult (R11 config).
// Grid (4 btiles x 2 ftiles, 33) = 264 CTAs, 256 thr, smem ~76KB ->
// 2 CTAs/SM. Tile 64b x 32f over 64 c; thread = 4b x 2f. W/Wsum stored
// transposed [c][f] so warp reads are contiguous; X reads broadcast.
//   Re = a1 - a2,  Im = a3 - a1 - a2
// ---------------------------------------------------------------------------
__global__ void __launch_bounds__(256) k_gemm() {
    extern __shared__ float smf[];
    float2* Xs    = (float2*)smf;                       // [64][66]
    float*  Xsum  = smf + 2 * 64 * 66;                  // [64][68]
    float2* Wt    = (float2*)(smf + 2 * 64 * 66 + 64 * 68);   // [64c][34f]
    float*  Wsumt = smf + 2 * 64 * 66 + 64 * 68 + 2 * 64 * 34; // [64c][36f]

    const int k  = blockIdx.y;
    const int b0 = (blockIdx.x & 3) * 64;
    const int f0 = (blockIdx.x >> 2) * 32;
    const float2* gX = g_Xf + k * (BSZ * CC) + b0 * CC;
    const float2* gW = g_Wf + k * (FF * CC) + f0 * CC;

#pragma unroll
    for (int i = threadIdx.x; i < 4096; i += 256) {
        const int r = i >> 6, c = i & 63;
        const float2 xv = gX[i];
        Xs[r * 66 + c] = xv;
        Xsum[r * 68 + c] = xv.x + xv.y;
    }
#pragma unroll
    for (int i = threadIdx.x; i < 2048; i += 256) {
        const int r = i >> 6, c = i & 63;   // r = f-row
        const float2 wv = gW[i];
        Wt[c * 34 + r] = wv;
        Wsumt[c * 36 + r] = wv.x + wv.y;
    }
    __syncthreads();

    const int tf = threadIdx.x & 15;   // f = f0 + tf + 16*i (i<2)
    const int tb = threadIdx.x >> 4;   // b = b0 + tb + 16*j (j<4)

    float a1[4][2] = {}, a2[4][2] = {}, a3[4][2] = {};
#pragma unroll 4
    for (int c = 0; c < 64; c += 2) {
        float4 xv[4];
        float2 xs[4];
#pragma unroll
        for (int j = 0; j < 4; j++) {
            const int b = tb + 16 * j;
            xv[j] = *(const float4*)&Xs[b * 66 + c];      // (re,im) x 2 c's
            xs[j] = *(const float2*)&Xsum[b * 68 + c];
        }
        float2 w0[2], w1[2];
        float  ws0[2], ws1[2];
#pragma unroll
        for (int i = 0; i < 2; i++) {
            const int f = tf + 16 * i;
            w0[i]  = Wt[c * 34 + f];
            w1[i]  = Wt[(c + 1) * 34 + f];
            ws0[i] = Wsumt[c * 36 + f];
            ws1[i] = Wsumt[(c + 1) * 36 + f];
        }
#pragma unroll
        for (int j = 0; j < 4; j++)
#pragma unroll
            for (int i = 0; i < 2; i++) {
                a1[j][i] = fmaf(xv[j].x, w0[i].x, a1[j][i]);
                a2[j][i] = fmaf(xv[j].y, w0[i].y, a2[j][i]);
                a3[j][i] = fmaf(xs[j].x, ws0[i],  a3[j][i]);
                a1[j][i] = fmaf(xv[j].z, w1[i].x, a1[j][i]);
                a2[j][i] = fmaf(xv[j].w, w1[i].y, a2[j][i]);
                a3[j][i] = fmaf(xs[j].y, ws1[i],  a3[j][i]);
            }
    }

    float2* gS = g_S + k * (BSZ * FF) + b0 * FF + f0;
#pragma unroll
    for (int j = 0; j < 4; j++)
#pragma unroll
        for (int i = 0; i < 2; i++) {
            const float re = a1[j][i] - a2[j][i];
            const float im = a3[j][i] - a1[j][i] - a2[j][i];
            gS[(tb + 16 * j) * FF + tf + 16 * i] = make_float2(re, im);
        }
}

// ---------------------------------------------------------------------------
// Kernel 3: real inverse transform with n / n+32 symmetry:
//   out[r][n]    = E[r][n] + O[r][n]
//   out[r][n+32] = E[r][n] - O[r][n]      (n < 32)
//   E over even k, O over odd k, Bm[k][n] = (s_k cos, -s_k sin),
//   s_k = 1/64 for k in {0,32} else 2/64.
// CTA = 32 rows x 256 thr -> 512 CTAs (~3.5/SM). Thread = (row, 4-wide n).
// ---------------------------------------------------------------------------
__global__ void __launch_bounds__(256) k_inv(float* __restrict__ out) {
    __shared__ float2 Ssh[32][NF];   // [row][k]
    __shared__ float2 Bm[NF][32];    // n < 32 only
    __shared__ float2 tw[64];

    const int t = threadIdx.x;
    if (t < 64) {
        float s, c;
        sincospif((float)t * (1.0f / 32.0f), &s, &c);
        tw[t] = make_float2(c, s);
    }
    __syncthreads();
#pragma unroll
    for (int i = t; i < NF * 32; i += 256) {
        const int k = i >> 5, n = i & 31;
        const float sc = (k == 0 || k == 32) ? (1.0f / 64.0f) : (2.0f / 64.0f);
        const float2 wv = tw[(k * n) & 63];
        Bm[k][n] = make_float2(sc * wv.x, -sc * wv.y);
    }

    const int r0 = blockIdx.x * 32;
#pragma unroll
    for (int i = t; i < 32 * NF; i += 256) {
        const int rl = i & 31, k = i >> 5;
        Ssh[rl][k] = g_S[k * (BSZ * FF) + r0 + rl];
    }
    __syncthreads();

    const int ng  = t & 7;    // n = ng*4 .. ng*4+3 (lower half)
    const int row = t >> 3;   // 0..31

    float e[4] = {}, o[4] = {};
#pragma unroll
    for (int kk = 0; kk < 17; kk++) {          // even k = 0,2,...,32
        const int k = 2 * kk;
        const float2 sv = Ssh[row][k];
        const float4 b01 = *(const float4*)&Bm[k][ng * 4];
        const float4 b23 = *(const float4*)&Bm[k][ng * 4 + 2];
        e[0] = fmaf(sv.x, b01.x, e[0]);  e[0] = fmaf(sv.y, b01.y, e[0]);
        e[1] = fmaf(sv.x, b01.z, e[1]);  e[1] = fmaf(sv.y, b01.w, e[1]);
        e[2] = fmaf(sv.x, b23.x, e[2]);  e[2] = fmaf(sv.y, b23.y, e[2]);
        e[3] = fmaf(sv.x, b23.z, e[3]);  e[3] = fmaf(sv.y, b23.w, e[3]);
    }
#pragma unroll
    for (int kk = 0; kk < 16; kk++) {          // odd k = 1,3,...,31
        const int k = 2 * kk + 1;
        const float2 sv = Ssh[row][k];
        const float4 b01 = *(const float4*)&Bm[k][ng * 4];
        const float4 b23 = *(const float4*)&Bm[k][ng * 4 + 2];
        o[0] = fmaf(sv.x, b01.x, o[0]);  o[0] = fmaf(sv.y, b01.y, o[0]);
        o[1] = fmaf(sv.x, b01.z, o[1]);  o[1] = fmaf(sv.y, b01.w, o[1]);
        o[2] = fmaf(sv.x, b23.x, o[2]);  o[2] = fmaf(sv.y, b23.y, o[2]);
        o[3] = fmaf(sv.x, b23.z, o[3]);  o[3] = fmaf(sv.y, b23.w, o[3]);
    }

    float* obase = out + (r0 + row) * 64 + ng * 4;
    *(float4*)obase = make_float4(e[0] + o[0], e[1] + o[1],
                                  e[2] + o[2], e[3] + o[3]);
    *(float4*)(obase + 32) = make_float4(e[0] - o[0], e[1] - o[1],
                                         e[2] - o[2], e[3] - o[3]);
}

// ---------------------------------------------------------------------------
extern "C" void kernel_launch(void* const* d_in, const int* in_sizes, int n_in,
                              void* d_out, int out_size) {
    const float* x = (const float*)d_in[0];
    const float* w = (const float*)d_in[1];
    // Defensive: identify by element count (x = 1048576, w = 262144).
    if (n_in >= 2 && in_sizes[0] == 64 * 64 * 64) {
        x = (const float*)d_in[1];
        w = (const float*)d_in[0];
    }

    // Xs 33792 + Xsum 17408 + Wt 17408 + Wsumt 9216 = 77824 bytes
    static const size_t gemm_smem =
        (2 * 64 * 66 + 64 * 68 + 2 * 64 * 34 + 64 * 36) * sizeof(float);
    cudaFuncSetAttribute(k_gemm, cudaFuncAttributeMaxDynamicSharedMemorySize,
                         (int)gemm_smem);

    // 20480 rows total (4096 weight rows + 16384 x rows), 32 rows per CTA.
    k_dft<<<640, 128>>>(x, w);
    k_gemm<<<dim3(8, 33), 256, gemm_smem>>>();
    k_inv<<<512, 256>>>((float*)d_out);
}